// round 1
// baseline (speedup 1.0000x reference)
#include <cuda_runtime.h>
#include <cstdint>

#define BB   8192   // batch (rows of K, rows of z/h)
#define NN   512    // h columns
#define DD   8      // z feature dim
#define BM   128
#define BN   128
#define BK   32

// -log2(e) / (2 * SIGMA_I^2) = -1.4426950408889634 / 2.88
#define C_EXP  (-0.5009357781f)
#define GAIN_F (0.05f)
#define EPS_F  (1e-6f)

// Dynamic smem layout (floats):
//   s_K   : BK * 2*BM  = 8192   (K tile, each value duplicated {k,k})
//   s_h   : BK * BN    = 4096
//   s_zj  : BK * 8     = 256
//   s_sqj : BK         = 32
//   s_rs  : BM         = 128
#define SMEM_FLOATS (BK*2*BM + BK*BN + BK*8 + BK + BM)
#define SMEM_BYTES  (SMEM_FLOATS * 4)

__global__ __launch_bounds__(256, 2)
void ei_fused_kernel(const float* __restrict__ z,
                     const float* __restrict__ h,
                     float* __restrict__ out)
{
    extern __shared__ float smem[];
    float* s_K   = smem;                       // [BK][2*BM]
    float* s_h   = s_K  + BK * 2 * BM;         // [BK][BN]
    float* s_zj  = s_h  + BK * BN;             // [BK][8]
    float* s_sqj = s_zj + BK * 8;              // [BK]
    float* s_rs  = s_sqj + BK;                 // [BM]

    const int tid = threadIdx.x;
    const int i0  = blockIdx.x * BM;
    const int n0  = blockIdx.y * BN;

    // ---- K-compute mapping: this thread owns row (tid&127), j-half (tid>>7)
    const int krow = tid & 127;
    const int jh   = tid >> 7;

    // per-thread z_i row (reused for all 256 j-tiles)
    float zi[8];
    {
        const float4* zp = (const float4*)(z + (size_t)(i0 + krow) * DD);
        float4 a = zp[0], b = zp[1];
        zi[0]=a.x; zi[1]=a.y; zi[2]=a.z; zi[3]=a.w;
        zi[4]=b.x; zi[5]=b.y; zi[6]=b.z; zi[7]=b.w;
    }
    float sqi = 0.f;
    #pragma unroll
    for (int d = 0; d < 8; d++) sqi = fmaf(zi[d], zi[d], sqi);

    if (tid < BM) s_rs[tid] = 0.f;

    // ---- GEMM mapping: 16x16 thread grid, 8x8 micro-tile (4 f32x2 col pairs)
    const int r0 = (tid >> 4) << 3;   // row offset 0..120
    const int c0 = (tid & 15) << 3;   // col offset 0..120

    unsigned long long acc[8][4];
    #pragma unroll
    for (int i = 0; i < 8; i++)
        #pragma unroll
        for (int q = 0; q < 4; q++) acc[i][q] = 0ull;

    for (int j0 = 0; j0 < BB; j0 += BK) {
        __syncthreads();   // previous GEMM done before smem overwrite

        // load z_j tile + self-squares (threads 0..31)
        if (tid < BK) {
            const float4* zp = (const float4*)(z + (size_t)(j0 + tid) * DD);
            float4 a = zp[0], b = zp[1];
            float* dst = s_zj + tid * 8;
            ((float4*)dst)[0] = a;
            ((float4*)dst)[1] = b;
            s_sqj[tid] = a.x*a.x + a.y*a.y + a.z*a.z + a.w*a.w
                       + b.x*b.x + b.y*b.y + b.z*b.z + b.w*b.w;
        }
        // load h tile [BK][BN] (all threads, 4x float4 each, coalesced)
        #pragma unroll
        for (int k = 0; k < 4; k++) {
            int fid = tid + k * 256;
            int jj  = fid >> 5;
            int cc  = (fid & 31) << 2;
            *(float4*)(s_h + jj * BN + cc) =
                *(const float4*)(h + (size_t)(j0 + jj) * NN + n0 + cc);
        }
        __syncthreads();

        // ---- compute K tile (duplicated layout) + rowsum partial
        float rs = 0.f;
        #pragma unroll
        for (int jj = 0; jj < 16; jj++) {
            const int j = jh * 16 + jj;
            const float4* zjp = (const float4*)(s_zj + j * 8);
            float4 a = zjp[0], b = zjp[1];
            float dot = zi[0]*a.x;
            dot = fmaf(zi[1], a.y, dot);
            dot = fmaf(zi[2], a.z, dot);
            dot = fmaf(zi[3], a.w, dot);
            dot = fmaf(zi[4], b.x, dot);
            dot = fmaf(zi[5], b.y, dot);
            dot = fmaf(zi[6], b.z, dot);
            dot = fmaf(zi[7], b.w, dot);
            float d2 = fmaxf(sqi + s_sqj[j] - 2.f * dot, 0.f);
            // t = exp(-d2 / (2*sigma_i^2));  exp(-d2/(2*sigma_e^2)) = t^4 (sigma_i = 2*sigma_e)
            float t;
            asm("ex2.approx.ftz.f32 %0, %1;" : "=f"(t) : "f"(d2 * C_EXP));
            float t2 = t * t;
            float kv = fmaf(0.8f * t2, t2, -t);   // K_E*t^4 - K_I*t
            rs += kv;
            unsigned long long kk2;
            asm("mov.b64 %0, {%1, %1};" : "=l"(kk2) : "f"(kv));
            *(unsigned long long*)(s_K + j * (2 * BM) + 2 * krow) = kk2;
        }
        atomicAdd(&s_rs[krow], rs);
        __syncthreads();

        // ---- GEMM accumulate: acc += K_tile @ h_tile  (f32x2 packed FMA)
        #pragma unroll
        for (int kk = 0; kk < BK; kk++) {
            unsigned long long apair[8];
            const float* aK = s_K + kk * (2 * BM) + 2 * r0;
            #pragma unroll
            for (int q = 0; q < 4; q++) {
                ulonglong2 v = *(const ulonglong2*)(aK + 4 * q);
                apair[2*q]   = v.x;   // {K[r0+2q],   K[r0+2q]}
                apair[2*q+1] = v.y;   // {K[r0+2q+1], K[r0+2q+1]}
            }
            unsigned long long bpair[4];
            const float* bH = s_h + kk * BN + c0;
            {
                ulonglong2 v0 = *(const ulonglong2*)(bH);
                ulonglong2 v1 = *(const ulonglong2*)(bH + 4);
                bpair[0] = v0.x; bpair[1] = v0.y;
                bpair[2] = v1.x; bpair[3] = v1.y;
            }
            #pragma unroll
            for (int i = 0; i < 8; i++)
                #pragma unroll
                for (int q = 0; q < 4; q++)
                    asm("fma.rn.f32x2 %0, %1, %2, %0;"
                        : "+l"(acc[i][q]) : "l"(apair[i]), "l"(bpair[q]));
        }
    }

    __syncthreads();   // s_rs complete & visible

    // ---- epilogue: out = GAIN * acc / (rowsum + eps)
    #pragma unroll
    for (int i = 0; i < 8; i++) {
        const int r = r0 + i;
        const float scale = GAIN_F / (s_rs[r] + EPS_F);
        float o[8];
        #pragma unroll
        for (int q = 0; q < 4; q++) {
            float lo, hi;
            asm("mov.b64 {%0, %1}, %2;" : "=f"(lo), "=f"(hi) : "l"(acc[i][q]));
            o[2*q]   = lo * scale;
            o[2*q+1] = hi * scale;
        }
        float* op = out + (size_t)(i0 + r) * NN + n0 + c0;
        ((float4*)op)[0] = make_float4(o[0], o[1], o[2], o[3]);
        ((float4*)op)[1] = make_float4(o[4], o[5], o[6], o[7]);
    }
}

extern "C" void kernel_launch(void* const* d_in, const int* in_sizes, int n_in,
                              void* d_out, int out_size)
{
    (void)in_sizes; (void)n_in; (void)out_size;
    const float* z = (const float*)d_in[0];   // [8192, 8]
    const float* h = (const float*)d_in[1];   // [8192, 512]
    float* out = (float*)d_out;               // [8192, 512]

    cudaFuncSetAttribute(ei_fused_kernel,
                         cudaFuncAttributeMaxDynamicSharedMemorySize, SMEM_BYTES);
    dim3 grid(BB / BM, NN / BN);              // 64 x 4 = 256 CTAs
    ei_fused_kernel<<<grid, 256, SMEM_BYTES>>>(z, h, out);
}

// round 4
// speedup vs baseline: 3.1962x; 3.1962x over previous
#include <cuda_runtime.h>
#include <cuda_bf16.h>
#include <cstdint>

#define BB 8192
#define NN 512
#define BM 128
#define BN 256
#define BK 64
#define NSTG (BB / BK)     // 128
#define THREADS 512

#define C_EXP  (-0.5009357781f)   // -log2(e)/(2*sigma_i^2), sigma_i = 2*sigma_e
#define GAIN_F (0.05f)
#define EPS_F  (1e-6f)

// ---- smem layout (bytes) ----
// A (K tile): [2 buf][hi,lo][128 rows][64 cols] bf16, 128B rows, SW128 swizzle
#define OFF_A        0
#define A_HL_STRIDE  16384
#define A_BUF_STRIDE 32768
// B (h tile): [2 buf][hi,lo][64 rows][256 cols] bf16, 512B rows, per-row swizzle
#define OFF_B        65536
#define B_HL_STRIDE  32768
#define B_BUF_STRIDE 65536
#define OFF_RS       (OFF_B + 131072)
#define SMEM_TOTAL   (OFF_RS + 512)   // 197120 B

// prepass outputs: h split into bf16 hi + bf16 residual, same [8192][512] layout
__device__ uint32_t g_hhi[BB * NN / 2];
__device__ uint32_t g_hlo[BB * NN / 2];

// ---- helpers ----
__device__ __forceinline__ uint32_t swA(uint32_t off) {         // 128B-row swizzle
    return off ^ ((off >> 3) & 0x70);
}
__device__ __forceinline__ uint32_t swB(uint32_t off) {         // 512B-row: chunk ^= (j&7)
    return off ^ ((off >> 5) & 0x70);
}
__device__ __forceinline__ uint32_t smem_u32(const void* p) {
    uint32_t a;
    asm("{ .reg .u64 t; cvta.to.shared.u64 t, %1; cvt.u32.u64 %0, t; }" : "=r"(a) : "l"(p));
    return a;
}
__device__ __forceinline__ void ldsm4(uint32_t* r, uint32_t a) {
    asm volatile("ldmatrix.sync.aligned.m8n8.x4.shared.b16 {%0,%1,%2,%3}, [%4];"
        : "=r"(r[0]), "=r"(r[1]), "=r"(r[2]), "=r"(r[3]) : "r"(a));
}
__device__ __forceinline__ void ldsm4t(uint32_t* r, uint32_t a) {
    asm volatile("ldmatrix.sync.aligned.m8n8.x4.trans.shared.b16 {%0,%1,%2,%3}, [%4];"
        : "=r"(r[0]), "=r"(r[1]), "=r"(r[2]), "=r"(r[3]) : "r"(a));
}
__device__ __forceinline__ void mma_bf16(float* c, const uint32_t* a, const uint32_t* b) {
    asm volatile("mma.sync.aligned.m16n8k16.row.col.f32.bf16.bf16.f32 "
        "{%0,%1,%2,%3}, {%4,%5,%6,%7}, {%8,%9}, {%0,%1,%2,%3};"
        : "+f"(c[0]), "+f"(c[1]), "+f"(c[2]), "+f"(c[3])
        : "r"(a[0]), "r"(a[1]), "r"(a[2]), "r"(a[3]), "r"(b[0]), "r"(b[1]));
}
#define CP16(dst, src) \
    asm volatile("cp.async.cg.shared.global [%0], [%1], 16;" :: "r"(dst), "l"(src) : "memory")
#define CPCOMMIT() asm volatile("cp.async.commit_group;" ::: "memory")
#define CPWAIT0()  asm volatile("cp.async.wait_group 0;" ::: "memory")

// ---- prepass: h f32 -> (hi, lo) bf16 pairs, same layout ----
__global__ void split_h(const float* __restrict__ h) {
    int idx = blockIdx.x * blockDim.x + threadIdx.x;   // float4 index, 1M total
    float4 v = ((const float4*)h)[idx];
    uint32_t h0, h1, l0, l1;
    asm("cvt.rn.bf16x2.f32 %0, %1, %2;" : "=r"(h0) : "f"(v.y), "f"(v.x));
    asm("cvt.rn.bf16x2.f32 %0, %1, %2;" : "=r"(h1) : "f"(v.w), "f"(v.z));
    float fx = __uint_as_float(h0 << 16);
    float fy = __uint_as_float(h0 & 0xffff0000u);
    float fz = __uint_as_float(h1 << 16);
    float fw = __uint_as_float(h1 & 0xffff0000u);
    asm("cvt.rn.bf16x2.f32 %0, %1, %2;" : "=r"(l0) : "f"(v.y - fy), "f"(v.x - fx));
    asm("cvt.rn.bf16x2.f32 %0, %1, %2;" : "=r"(l1) : "f"(v.w - fw), "f"(v.z - fz));
    ((uint2*)g_hhi)[idx] = make_uint2(h0, h1);
    ((uint2*)g_hlo)[idx] = make_uint2(l0, l1);
}

// ---- main fused kernel ----
__global__ __launch_bounds__(THREADS)
void ei_hmma_kernel(const float* __restrict__ z, float* __restrict__ out)
{
    extern __shared__ char smem[];
    const uint32_t sb = smem_u32(smem);
    float* srs = (float*)(smem + OFF_RS);

    const int tid  = threadIdx.x;
    const int lane = tid & 31;
    const int wid  = tid >> 5;          // 0..15
    const int wm   = wid & 3;           // warp m index (4)
    const int wn   = wid >> 2;          // warp n index (4)
    const int i0   = blockIdx.x * BM;
    const int n0   = blockIdx.y * BN;

    if (tid < BM) srs[tid] = 0.f;

    // ---- K-gen identity: 2 rows x 8 j per thread ----
    const int i_loc = wid * 8 + (lane & 3) * 2;   // CTA-local rows i_loc, i_loc+1
    const int j_loc = (lane >> 2) * 8;            // stage-local j block (0..56)

    float zi0[8], zi1[8];
    {
        const float4* p0 = (const float4*)(z + (size_t)(i0 + i_loc) * 8);
        const float4* p1 = (const float4*)(z + (size_t)(i0 + i_loc + 1) * 8);
        float4 a = p0[0], b = p0[1], c = p1[0], d = p1[1];
        zi0[0]=a.x; zi0[1]=a.y; zi0[2]=a.z; zi0[3]=a.w;
        zi0[4]=b.x; zi0[5]=b.y; zi0[6]=b.z; zi0[7]=b.w;
        zi1[0]=c.x; zi1[1]=c.y; zi1[2]=c.z; zi1[3]=c.w;
        zi1[4]=d.x; zi1[5]=d.y; zi1[6]=d.z; zi1[7]=d.w;
    }
    float sqi0 = 0.f, sqi1 = 0.f;
    #pragma unroll
    for (int d = 0; d < 8; d++) {
        sqi0 = fmaf(zi0[d], zi0[d], sqi0);
        sqi1 = fmaf(zi1[d], zi1[d], sqi1);
    }
    float rs0 = 0.f, rs1 = 0.f;

    float acc[2][8][4];
    #pragma unroll
    for (int mt = 0; mt < 2; mt++)
        #pragma unroll
        for (int nt = 0; nt < 8; nt++)
            #pragma unroll
            for (int q = 0; q < 4; q++) acc[mt][nt][q] = 0.f;

    // ---------------- produce(stage, buf): cp.async B + K-gen A ----------------
    #define LOADB(st, buf) do {                                                   \
        const int jg0 = (st) * BK;                                                \
        _Pragma("unroll")                                                         \
        for (int k = 0; k < 4; k++) {                                             \
            int c = tid + k * 512;                                                \
            int j = c >> 5, nc = c & 31;                                          \
            size_t gidx = ((size_t)(jg0 + j) * NN + n0 + nc * 8) >> 1;            \
            uint32_t sw = swB((uint32_t)(j * 512 + nc * 16));                     \
            uint32_t dst = sb + OFF_B + (buf) * B_BUF_STRIDE + sw;                \
            CP16(dst, (const char*)g_hhi + gidx * 4);                             \
            CP16(dst + B_HL_STRIDE, (const char*)g_hlo + gidx * 4);               \
        }                                                                         \
        CPCOMMIT();                                                               \
    } while (0)

    #define KGEN(st, buf) do {                                                    \
        const int jg0 = (st) * BK + j_loc;                                        \
        float kv0[8], kv1[8];                                                     \
        _Pragma("unroll")                                                         \
        for (int jj = 0; jj < 8; jj++) {                                          \
            const float4* zr = (const float4*)(z + (size_t)(jg0 + jj) * 8);       \
            float4 a = zr[0], b = zr[1];                                          \
            float zj[8] = {a.x, a.y, a.z, a.w, b.x, b.y, b.z, b.w};               \
            float sqj = 0.f, d0 = 0.f, d1 = 0.f;                                  \
            _Pragma("unroll")                                                     \
            for (int d = 0; d < 8; d++) {                                         \
                sqj = fmaf(zj[d], zj[d], sqj);                                    \
                d0  = fmaf(zi0[d], zj[d], d0);                                    \
                d1  = fmaf(zi1[d], zj[d], d1);                                    \
            }                                                                     \
            float e0 = fminf(fmaf(-2.f, d0, sqi0 + sqj) * C_EXP, 0.f);            \
            float e1 = fminf(fmaf(-2.f, d1, sqi1 + sqj) * C_EXP, 0.f);            \
            float t0, t1;                                                         \
            asm("ex2.approx.ftz.f32 %0, %1;" : "=f"(t0) : "f"(e0));               \
            asm("ex2.approx.ftz.f32 %0, %1;" : "=f"(t1) : "f"(e1));               \
            float t02 = t0 * t0, t12 = t1 * t1;                                   \
            kv0[jj] = fmaf(0.8f * t02, t02, -t0);                                 \
            kv1[jj] = fmaf(0.8f * t12, t12, -t1);                                 \
            rs0 += kv0[jj]; rs1 += kv1[jj];                                       \
        }                                                                         \
        uint32_t abase = sb + OFF_A + (buf) * A_BUF_STRIDE;                       \
        _Pragma("unroll")                                                         \
        for (int r = 0; r < 2; r++) {                                             \
            const float* kv = r ? kv1 : kv0;                                      \
            uint32_t hi[4], lo[4];                                                \
            _Pragma("unroll")                                                     \
            for (int q = 0; q < 4; q++) {                                         \
                asm("cvt.rn.bf16x2.f32 %0, %1, %2;"                               \
                    : "=r"(hi[q]) : "f"(kv[2*q+1]), "f"(kv[2*q]));                \
                float f0 = __uint_as_float(hi[q] << 16);                          \
                float f1 = __uint_as_float(hi[q] & 0xffff0000u);                  \
                asm("cvt.rn.bf16x2.f32 %0, %1, %2;"                               \
                    : "=r"(lo[q]) : "f"(kv[2*q+1] - f1), "f"(kv[2*q] - f0));      \
            }                                                                     \
            uint32_t sw = swA((uint32_t)(i_loc + r) * 128u + (uint32_t)j_loc * 2u); \
            asm volatile("st.shared.v4.b32 [%0], {%1,%2,%3,%4};"                  \
                :: "r"(abase + sw), "r"(hi[0]), "r"(hi[1]), "r"(hi[2]), "r"(hi[3]) : "memory"); \
            asm volatile("st.shared.v4.b32 [%0], {%1,%2,%3,%4};"                  \
                :: "r"(abase + A_HL_STRIDE + sw), "r"(lo[0]), "r"(lo[1]), "r"(lo[2]), "r"(lo[3]) : "memory"); \
        }                                                                         \
    } while (0)

    // ---- prologue: produce stage 0 ----
    LOADB(0, 0);
    KGEN(0, 0);
    CPWAIT0();
    __syncthreads();

    // lane-invariant ldsm address pieces
    const uint32_t a_row = (uint32_t)(wm * 32 + (lane & 15));
    const uint32_t a_cb  = (uint32_t)((lane >> 4) * 16);
    const uint32_t b_rl  = (uint32_t)(lane & 15);
    const uint32_t b_cb  = (uint32_t)((wn * 64 + ((lane >> 4) << 3)) * 2);

    // ---- main loop ----
    for (int s = 0; s < NSTG; s++) {
        const int buf = s & 1;
        if (s + 1 < NSTG) LOADB(s + 1, buf ^ 1);

        // MMA(stage s)
        {
            uint32_t abase = sb + OFF_A + buf * A_BUF_STRIDE;
            uint32_t bbase = sb + OFF_B + buf * B_BUF_STRIDE;
            #pragma unroll
            for (int ks = 0; ks < 4; ks++) {
                uint32_t ahi[2][4], alo[2][4];
                #pragma unroll
                for (int mt = 0; mt < 2; mt++) {
                    uint32_t sw = swA((a_row + mt * 16) * 128u + (uint32_t)(ks * 32) + a_cb);
                    ldsm4(ahi[mt], abase + sw);
                    ldsm4(alo[mt], abase + A_HL_STRIDE + sw);
                }
                uint32_t boff = (uint32_t)(ks * 16 + b_rl) * 512u + b_cb;
                #pragma unroll
                for (int g = 0; g < 4; g++) {
                    uint32_t sw = swB(boff + (uint32_t)(g * 32));
                    uint32_t bh[4], bl[4];
                    ldsm4t(bh, bbase + sw);
                    #pragma unroll
                    for (int mt = 0; mt < 2; mt++) {
                        mma_bf16(acc[mt][2*g],     ahi[mt], bh);
                        mma_bf16(acc[mt][2*g + 1], ahi[mt], bh + 2);
                        mma_bf16(acc[mt][2*g],     alo[mt], bh);
                        mma_bf16(acc[mt][2*g + 1], alo[mt], bh + 2);
                    }
                    ldsm4t(bl, bbase + B_HL_STRIDE + sw);
                    #pragma unroll
                    for (int mt = 0; mt < 2; mt++) {
                        mma_bf16(acc[mt][2*g],     ahi[mt], bl);
                        mma_bf16(acc[mt][2*g + 1], ahi[mt], bl + 2);
                    }
                }
            }
        }

        if (s + 1 < NSTG) KGEN(s + 1, buf ^ 1);
        CPWAIT0();
        __syncthreads();
    }

    // ---- rowsum reduce + epilogue ----
    atomicAdd(&srs[i_loc],     rs0);
    atomicAdd(&srs[i_loc + 1], rs1);
    __syncthreads();

    #pragma unroll
    for (int mt = 0; mt < 2; mt++) {
        const int r1 = wm * 32 + mt * 16 + (lane >> 2);
        const int r2 = r1 + 8;
        const float sc1 = GAIN_F / (srs[r1] + EPS_F);
        const float sc2 = GAIN_F / (srs[r2] + EPS_F);
        float* o1 = out + (size_t)(i0 + r1) * NN + n0 + wn * 64 + (lane & 3) * 2;
        float* o2 = out + (size_t)(i0 + r2) * NN + n0 + wn * 64 + (lane & 3) * 2;
        #pragma unroll
        for (int nt = 0; nt < 8; nt++) {
            *(float2*)(o1 + nt * 8) = make_float2(acc[mt][nt][0] * sc1, acc[mt][nt][1] * sc1);
            *(float2*)(o2 + nt * 8) = make_float2(acc[mt][nt][2] * sc2, acc[mt][nt][3] * sc2);
        }
    }
}

extern "C" void kernel_launch(void* const* d_in, const int* in_sizes, int n_in,
                              void* d_out, int out_size)
{
    (void)in_sizes; (void)n_in; (void)out_size;
    const float* z = (const float*)d_in[0];   // [8192, 8]
    const float* h = (const float*)d_in[1];   // [8192, 512]
    float* out = (float*)d_out;

    split_h<<<BB * NN / 4 / 256, 256>>>(h);

    cudaFuncSetAttribute(ei_hmma_kernel,
                         cudaFuncAttributeMaxDynamicSharedMemorySize, SMEM_TOTAL);
    ei_hmma_kernel<<<dim3(BB / BM, NN / BN), THREADS, SMEM_TOTAL>>>(z, out);
}